// round 5
// baseline (speedup 1.0000x reference)
#include <cuda_runtime.h>
#include <cstdint>
#include <cstddef>

#define NN 50000
#define DD 64
#define EE 800000
#define ND (NN*DD)

// -------- scratch (static device globals: allocation-free) --------
static __device__ float g_deg[NN];
static __device__ int   g_cnt[NN];
static __device__ int   g_cursor[NN];
static __device__ int   g_off[NN+1];
static __device__ int   g_csc_src[EE];
static __device__ float g_csc_w[EE];
static __device__ float g_X1[ND], g_X2[ND];
static __device__ float g_H1[ND], g_H2[ND];
static __device__ float g_HR[ND], g_HR1[ND], g_HR2[ND];
static __device__ float g_Z[ND], g_Gx[ND];
static __device__ int   g_is32;

__device__ __forceinline__ float* buf(int s){
    switch(s){
        case 0: return g_X1;  case 1: return g_X2;
        case 2: return g_H1;  case 3: return g_H2;
        case 4: return g_HR;  case 5: return g_HR1;
        case 6: return g_HR2; default: return g_X1;
    }
}

// edge_index may be int64 (as written) or int32 (JAX without x64). g_is32 set per-call.
__device__ __forceinline__ int eidx(const void* ei, int half, int e){
    if (g_is32) return ((const int*)ei)[half*EE + e];
    return (int)((const long long*)ei)[half*EE + e];
}

// -------- dtype detector --------
// int64 node ids < 2^32: every odd 32-bit word is 0. int32 data: odd words are
// node ids, all-zero only with probability ~(2e-5)^64 ~ 0.
__global__ void k_detect(const void* ei){
    if (threadIdx.x == 0 && blockIdx.x == 0){
        const unsigned* p = (const unsigned*)ei;
        int is32 = 0;
        for (int i = 0; i < 64; i++){
            if (p[2*i+1] != 0u){ is32 = 1; break; }
        }
        g_is32 = is32;
    }
}

__global__ void k_zero(){
    int i = blockIdx.x*blockDim.x + threadIdx.x;
    if (i < NN){ g_deg[i] = 0.f; g_cnt[i] = 0; g_cursor[i] = 0; }
}

// one edge pass: weighted out-degree by src + in-degree histogram by dst
__global__ void k_hist(const void* __restrict__ ei, const float* __restrict__ w){
    int e = blockIdx.x*blockDim.x + threadIdx.x;
    if (e >= EE) return;
    atomicAdd(&g_deg[eidx(ei,0,e)], w[e]);
    atomicAdd(&g_cnt[eidx(ei,1,e)], 1);
}

// exclusive prefix scan of g_cnt -> g_off (single block, 1024 threads)
__global__ __launch_bounds__(1024) void k_scan(){
    __shared__ int ssum[1024];
    const int seg = (NN + 1023)/1024;     // 49
    int t  = threadIdx.x;
    int lo = t*seg;
    int hi = lo + seg; if (hi > NN) hi = NN; if (lo > NN) lo = NN;
    int s = 0;
    for (int i = lo; i < hi; i++) s += g_cnt[i];
    ssum[t] = s;
    __syncthreads();
    for (int off = 1; off < 1024; off <<= 1){
        int v = (t >= off) ? ssum[t-off] : 0;
        __syncthreads();
        ssum[t] += v;
        __syncthreads();
    }
    int run = (t == 0) ? 0 : ssum[t-1];
    for (int i = lo; i < hi; i++){ g_off[i] = run; run += g_cnt[i]; }
    if (t == 0) g_off[NN] = EE;
}

// one edge pass: compute sym-norm coefficient and place edge into CSC slot
__global__ void k_place(const void* __restrict__ ei, const float* __restrict__ w){
    int e = blockIdx.x*blockDim.x + threadIdx.x;
    if (e >= EE) return;
    int s = eidx(ei,0,e), d = eidx(ei,1,e);
    float ds = g_deg[s], dd = g_deg[d];
    float rs = ds > 0.f ? rsqrtf(ds) : 0.f;
    float rd = dd > 0.f ? rsqrtf(dd) : 0.f;
    int pos = g_off[d] + atomicAdd(&g_cursor[d], 1);
    g_csc_src[pos] = s;
    g_csc_w[pos]   = w[e] * rs * rd;
}

// ---- gather propagation (warp per node, fused init, shfl-batched edges):
//   out[d,:] = aScale*(c-1)*u[d,:] + bcoef*t[d,:] - aScale*c * sum_e norm_e * u[src_e,:]
__global__ __launch_bounds__(256) void k_gather2(
        int outA, const float* uAe, int uAs, const float* tA,
        int outB, const float* uBe, int uBs, const float* tB,
        float aScale, float bcoef, const float* __restrict__ lam){
    int node = (blockIdx.x*blockDim.x + threadIdx.x) >> 5;
    int l    = threadIdx.x & 31;              // lane: float2 chunk (8B) -> 64 floats/warp
    if (node >= NN) return;
    const float* uA = uAe ? uAe : buf(uAs);
    const float* uB = uBe ? uBe : buf(uBs);
    int beg = g_off[node], end = g_off[node+1];
    float2 accA = {0.f,0.f}, accB = {0.f,0.f};
    for (int base = beg; base < end; base += 32){
        int n = end - base; if (n > 32) n = 32;
        int   sl = 0; float wl = 0.f;
        if (l < n){ sl = g_csc_src[base + l]; wl = g_csc_w[base + l]; }
        #pragma unroll 4
        for (int k = 0; k < n; k++){
            int   s  = __shfl_sync(0xffffffffu, sl, k);
            float wv = __shfl_sync(0xffffffffu, wl, k);
            float2 a = *reinterpret_cast<const float2*>(uA + (size_t)s*DD + l*2);
            float2 b = *reinterpret_cast<const float2*>(uB + (size_t)s*DD + l*2);
            accA.x += wv*a.x; accA.y += wv*a.y;
            accB.x += wv*b.x; accB.y += wv*b.y;
        }
    }
    float c  = 2.f / lam[0];
    float ka = aScale*(c - 1.f);
    float kc = -aScale*c;
    size_t o = (size_t)node*DD + l*2;
    float2 ua = *reinterpret_cast<const float2*>(uA + o);
    float2 ub = *reinterpret_cast<const float2*>(uB + o);
    float2 ra, rb;
    ra.x = ka*ua.x + kc*accA.x;  ra.y = ka*ua.y + kc*accA.y;
    rb.x = ka*ub.x + kc*accB.x;  rb.y = ka*ub.y + kc*accB.y;
    if (tA){ const float2 t2 = *reinterpret_cast<const float2*>(tA + o); ra.x += bcoef*t2.x; ra.y += bcoef*t2.y; }
    if (tB){ const float2 t2 = *reinterpret_cast<const float2*>(tB + o); rb.x += bcoef*t2.x; rb.y += bcoef*t2.y; }
    *reinterpret_cast<float2*>(buf(outA) + o) = ra;
    *reinterpret_cast<float2*>(buf(outB) + o) = rb;
}

__global__ __launch_bounds__(256) void k_gather1(
        int outSel, const float* uExt, int uSel, const float* tExt, int tSel, int useT,
        float aScale, float bcoef, const float* __restrict__ lam){
    int node = (blockIdx.x*blockDim.x + threadIdx.x) >> 5;
    int l    = threadIdx.x & 31;
    if (node >= NN) return;
    const float* u = uExt ? uExt : buf(uSel);
    int beg = g_off[node], end = g_off[node+1];
    float2 acc = {0.f,0.f};
    for (int base = beg; base < end; base += 32){
        int n = end - base; if (n > 32) n = 32;
        int   sl = 0; float wl = 0.f;
        if (l < n){ sl = g_csc_src[base + l]; wl = g_csc_w[base + l]; }
        #pragma unroll 4
        for (int k = 0; k < n; k++){
            int   s  = __shfl_sync(0xffffffffu, sl, k);
            float wv = __shfl_sync(0xffffffffu, wl, k);
            float2 a = *reinterpret_cast<const float2*>(u + (size_t)s*DD + l*2);
            acc.x += wv*a.x; acc.y += wv*a.y;
        }
    }
    float c  = 2.f / lam[0];
    float ka = aScale*(c - 1.f);
    float kc = -aScale*c;
    size_t o = (size_t)node*DD + l*2;
    float2 uv = *reinterpret_cast<const float2*>(u + o);
    float2 r;
    r.x = ka*uv.x + kc*acc.x;  r.y = ka*uv.y + kc*acc.y;
    if (useT){
        const float* t = tExt ? tExt : buf(tSel);
        const float2 t2 = *reinterpret_cast<const float2*>(t + o);
        r.x += bcoef*t2.x; r.y += bcoef*t2.y;
    }
    *reinterpret_cast<float2*>(buf(outSel) + o) = r;
}

// ------- Fused Z / R / Gx GEMM + gate epilogue (register-blocked) -------
// 128 threads/block, 32-row tile. Thread (j = tid&31, rg = tid>>5) computes
// columns {j, j+32} x rows {rg*8 .. rg*8+7}. Inner iter: 8 LDS + 6 LDG + 48 FFMA.
// Z = sigmoid(M@Wz + b0+b1), R = sigmoid(M@Wr + b2+b3), Gx = M[:,:192]@W4 + b4, HR = H*R
__global__ __launch_bounds__(128) void k_gates(const float* __restrict__ X,
                                               const float* __restrict__ H,
                                               const float* __restrict__ W,
                                               const float* __restrict__ B){
    __shared__ float sm[32*384];   // 48 KB
    int tid = threadIdx.x;
    int r0  = blockIdx.x * 32;
    const float* vecs[6] = {X, g_X1, g_X2, H, g_H1, g_H2};
    for (int v = 0; v < 6; v++){
        const float* src = vecs[v];
        for (int i = tid; i < 32*64; i += 128){
            int r = i >> 6, cc = i & 63;
            int row = r0 + r;
            sm[r*384 + v*64 + cc] = (row < NN) ? src[(size_t)row*64 + cc] : 0.f;
        }
    }
    __syncthreads();

    int j  = tid & 31;              // columns j and j+32
    int rg = tid >> 5;              // 4 row-groups of 8 rows
    float accZ[2][8] = {}, accR[2][8] = {}, accG[2][8] = {};
    for (int v = 0; v < 6; v++){
        // conv_w layout: [6,3,64,64]; element (conv,k,i,j) at ((conv*3+k)*64+i)*64+j
        int kk = v % 3;
        const float* wZ = W + (size_t)(((v < 3 ? 0 : 1)*3 + kk)*64)*64 + j;
        const float* wR = W + (size_t)(((v < 3 ? 2 : 3)*3 + kk)*64)*64 + j;
        const float* wG = W + (size_t)((4*3 + kk)*64)*64 + j;
        bool hasG = (v < 3);
        for (int ii = 0; ii < 64; ii++){
            float wz0 = wZ[ii*64],      wz1 = wZ[ii*64 + 32];
            float wr0 = wR[ii*64],      wr1 = wR[ii*64 + 32];
            float wg0 = hasG ? wG[ii*64]      : 0.f;
            float wg1 = hasG ? wG[ii*64 + 32] : 0.f;
            const float* mrow = &sm[(rg*8)*384 + v*64 + ii];
            #pragma unroll
            for (int r = 0; r < 8; r++){
                float m = mrow[r*384];      // warp-broadcast LDS, reused 6x
                accZ[0][r] += m*wz0;  accZ[1][r] += m*wz1;
                accR[0][r] += m*wr0;  accR[1][r] += m*wr1;
                accG[0][r] += m*wg0;  accG[1][r] += m*wg1;
            }
        }
    }
    #pragma unroll
    for (int cpart = 0; cpart < 2; cpart++){
        int col = j + cpart*32;
        float bz = B[col] + B[64+col];
        float br = B[128+col] + B[192+col];
        float b4 = B[256+col];
        #pragma unroll
        for (int r = 0; r < 8; r++){
            int row = r0 + rg*8 + r;
            if (row < NN){
                size_t o = (size_t)row*64 + col;
                float z  = 1.f/(1.f + __expf(-(accZ[cpart][r] + bz)));
                float rr = 1.f/(1.f + __expf(-(accR[cpart][r] + br)));
                g_Z[o]  = z;
                g_Gx[o] = accG[cpart][r] + b4;
                g_HR[o] = H[o] * rr;
            }
        }
    }
}

// Gh = [HR,HR1,HR2]@W5 + b5; H_tilde = tanh(Gx+Gh); out = Z*H_tilde + (1-Z)*H
__global__ __launch_bounds__(256) void k_final(const float* __restrict__ H,
                                               const float* __restrict__ W,
                                               const float* __restrict__ B,
                                               float* __restrict__ out){
    __shared__ float sm[32*192];   // 24 KB
    int tid = threadIdx.x;
    int r0  = blockIdx.x * 32;
    const float* vecs[3] = {g_HR, g_HR1, g_HR2};
    for (int v = 0; v < 3; v++){
        const float* src = vecs[v];
        for (int i = tid; i < 32*64; i += 256){
            int r = i >> 6, cc = i & 63;
            int row = r0 + r;
            sm[r*192 + v*64 + cc] = (row < NN) ? src[(size_t)row*64 + cc] : 0.f;
        }
    }
    __syncthreads();

    int j  = tid & 63;
    int rg = tid >> 6;
    float acc[8] = {};
    for (int v = 0; v < 3; v++){
        const float* wp = W + (size_t)((5*3 + v)*64)*64 + j;
        for (int ii = 0; ii < 64; ii++){
            float wv = wp[ii*64];
            const float* mrow = &sm[(rg*8)*192 + v*64 + ii];
            #pragma unroll
            for (int r = 0; r < 8; r++) acc[r] += mrow[r*192]*wv;
        }
    }
    float b5 = B[320 + j];
    #pragma unroll
    for (int r = 0; r < 8; r++){
        int row = r0 + rg*8 + r;
        if (row < NN){
            size_t o = (size_t)row*64 + j;
            float ht = tanhf(g_Gx[o] + acc[r] + b5);
            float z  = g_Z[o];
            out[o] = z*ht + (1.f - z)*H[o];
        }
    }
}

extern "C" void kernel_launch(void* const* d_in, const int* in_sizes, int n_in,
                              void* d_out, int out_size){
    const float* X   = (const float*)d_in[0];
    const void*  ei  = d_in[1];
    const float* w   = (const float*)d_in[2];
    const float* H   = (const float*)d_in[3];
    const float* lam = (const float*)d_in[4];
    const float* W   = (const float*)d_in[5];
    const float* B   = (const float*)d_in[6];
    float* out = (float*)d_out;

    const int bN  = (NN + 255)/256;
    const int bE  = (EE + 255)/256;
    const int bGT = (NN*32 + 255)/256;     // warp-per-node gather: 6250 blocks
    const int bG  = (NN + 31)/32;          // 1563 blocks

    // ---- CSC build (per replay; graph-capturable) ----
    k_detect<<<1, 32>>>(ei);
    k_zero  <<<bN, 256>>>();
    k_hist  <<<bE, 256>>>(ei, w);
    k_scan  <<<1, 1024>>>();
    k_place <<<bE, 256>>>(ei, w);

    // ---- Chebyshev bases: T1 = (c-1)v - cAv ; T2 = 2(c-1)T1 - 2cAT1 - v ----
    k_gather2<<<bGT, 256>>>(0, X, 0, nullptr,      2, H, 0, nullptr,      1.f,  0.f, lam);
    k_gather2<<<bGT, 256>>>(1, nullptr, 0, X,      3, nullptr, 2, H,      2.f, -1.f, lam);

    // ---- Z, R, Gx, HR = H*R ----
    k_gates<<<bG, 128>>>(X, H, W, B);

    // ---- HR chain (depends on k_gates) ----
    k_gather1<<<bGT, 256>>>(5, nullptr, 4, nullptr, 0, 0, 1.f,  0.f, lam);
    k_gather1<<<bGT, 256>>>(6, nullptr, 5, nullptr, 4, 1, 2.f, -1.f, lam);

    // ---- Gh, H_tilde, output ----
    k_final<<<bG, 256>>>(H, W, B, out);
}

// round 7
// speedup vs baseline: 1.6172x; 1.6172x over previous
#include <cuda_runtime.h>
#include <cstdint>
#include <cstddef>

#define NN 50000
#define DD 64
#define EE 800000
#define ND (NN*DD)
#define NB 196            // ceil(NN/256)

// -------- scratch (static device globals: allocation-free) --------
static __device__ float g_deg[NN];
static __device__ int   g_cnt[NN];
static __device__ int   g_cursor[NN];
static __device__ int   g_part[256];
static __device__ int   g_off[NN+1];
static __device__ int   g_csc_src[EE];
static __device__ float g_csc_w[EE];
static __device__ float g_X1[ND], g_X2[ND];
static __device__ float g_H1[ND], g_H2[ND];
static __device__ float g_HR[ND], g_HR1[ND], g_HR2[ND];
static __device__ float g_Z[ND], g_Gx[ND];
static __device__ int   g_is32;

__device__ __forceinline__ float* buf(int s){
    switch(s){
        case 0: return g_X1;  case 1: return g_X2;
        case 2: return g_H1;  case 3: return g_H2;
        case 4: return g_HR;  case 5: return g_HR1;
        case 6: return g_HR2; default: return g_X1;
    }
}

// edge_index may be int64 (as written) or int32 (JAX without x64). g_is32 set per-call.
__device__ __forceinline__ int eidx(const void* ei, int half, int e){
    if (g_is32) return ((const int*)ei)[half*EE + e];
    return (int)((const long long*)ei)[half*EE + e];
}

// -------- dtype detector --------
__global__ void k_detect(const void* ei){
    if (threadIdx.x == 0 && blockIdx.x == 0){
        const unsigned* p = (const unsigned*)ei;
        int is32 = 0;
        for (int i = 0; i < 64; i++){
            if (p[2*i+1] != 0u){ is32 = 1; break; }
        }
        g_is32 = is32;
    }
}

__global__ void k_zero(){
    int i = blockIdx.x*blockDim.x + threadIdx.x;
    if (i < NN){ g_deg[i] = 0.f; g_cnt[i] = 0; g_cursor[i] = 0; }
}

// one edge pass: weighted out-degree by src + in-degree histogram by dst
__global__ void k_hist(const void* __restrict__ ei, const float* __restrict__ w){
    int e = blockIdx.x*blockDim.x + threadIdx.x;
    if (e >= EE) return;
    atomicAdd(&g_deg[eidx(ei,0,e)], w[e]);
    atomicAdd(&g_cnt[eidx(ei,1,e)], 1);
}

// ---- parallel 3-phase exclusive scan of g_cnt -> g_off (coalesced) ----
__global__ void k_scan1(){          // NB blocks x 256: per-block sums
    __shared__ int sred[256];
    int t = threadIdx.x;
    int idx = blockIdx.x*256 + t;
    sred[t] = (idx < NN) ? g_cnt[idx] : 0;
    __syncthreads();
    for (int s = 128; s > 0; s >>= 1){
        if (t < s) sred[t] += sred[t+s];
        __syncthreads();
    }
    if (t == 0) g_part[blockIdx.x] = sred[0];
}
__global__ void k_scan2(){          // 1 block x 256: exclusive scan of partials
    __shared__ int s[256];
    int t = threadIdx.x;
    int v = (t < NB) ? g_part[t] : 0;
    s[t] = v; __syncthreads();
    for (int off = 1; off < 256; off <<= 1){
        int u = (t >= off) ? s[t-off] : 0;
        __syncthreads();
        s[t] += u;
        __syncthreads();
    }
    g_part[t] = s[t] - v;           // exclusive
}
__global__ void k_scan3(){          // NB blocks x 256: local scan + base
    __shared__ int s[256];
    int t = threadIdx.x;
    int idx = blockIdx.x*256 + t;
    int v = (idx < NN) ? g_cnt[idx] : 0;
    s[t] = v; __syncthreads();
    for (int off = 1; off < 256; off <<= 1){
        int u = (t >= off) ? s[t-off] : 0;
        __syncthreads();
        s[t] += u;
        __syncthreads();
    }
    if (idx < NN) g_off[idx] = g_part[blockIdx.x] + s[t] - v;
    if (idx == 0) g_off[NN] = EE;
}

// one edge pass: compute sym-norm coefficient and place edge into CSC slot
__global__ void k_place(const void* __restrict__ ei, const float* __restrict__ w){
    int e = blockIdx.x*blockDim.x + threadIdx.x;
    if (e >= EE) return;
    int s = eidx(ei,0,e), d = eidx(ei,1,e);
    float ds = g_deg[s], dd = g_deg[d];
    float rs = ds > 0.f ? rsqrtf(ds) : 0.f;
    float rd = dd > 0.f ? rsqrtf(dd) : 0.f;
    int pos = g_off[d] + atomicAdd(&g_cursor[d], 1);
    g_csc_src[pos] = s;
    g_csc_w[pos]   = w[e] * rs * rd;
}

// ---- gather propagation (warp per node, fused init, shfl-batched edges) ----
__global__ __launch_bounds__(256) void k_gather2(
        int outA, const float* uAe, int uAs, const float* tA,
        int outB, const float* uBe, int uBs, const float* tB,
        float aScale, float bcoef, const float* __restrict__ lam){
    int node = (blockIdx.x*blockDim.x + threadIdx.x) >> 5;
    int l    = threadIdx.x & 31;
    if (node >= NN) return;
    const float* uA = uAe ? uAe : buf(uAs);
    const float* uB = uBe ? uBe : buf(uBs);
    int beg = g_off[node], end = g_off[node+1];
    float2 accA = {0.f,0.f}, accB = {0.f,0.f};
    for (int base = beg; base < end; base += 32){
        int n = end - base; if (n > 32) n = 32;
        int   sl = 0; float wl = 0.f;
        if (l < n){ sl = g_csc_src[base + l]; wl = g_csc_w[base + l]; }
        #pragma unroll 4
        for (int k = 0; k < n; k++){
            int   s  = __shfl_sync(0xffffffffu, sl, k);
            float wv = __shfl_sync(0xffffffffu, wl, k);
            float2 a = *reinterpret_cast<const float2*>(uA + (size_t)s*DD + l*2);
            float2 b = *reinterpret_cast<const float2*>(uB + (size_t)s*DD + l*2);
            accA.x += wv*a.x; accA.y += wv*a.y;
            accB.x += wv*b.x; accB.y += wv*b.y;
        }
    }
    float c  = 2.f / lam[0];
    float ka = aScale*(c - 1.f);
    float kc = -aScale*c;
    size_t o = (size_t)node*DD + l*2;
    float2 ua = *reinterpret_cast<const float2*>(uA + o);
    float2 ub = *reinterpret_cast<const float2*>(uB + o);
    float2 ra, rb;
    ra.x = ka*ua.x + kc*accA.x;  ra.y = ka*ua.y + kc*accA.y;
    rb.x = ka*ub.x + kc*accB.x;  rb.y = ka*ub.y + kc*accB.y;
    if (tA){ const float2 t2 = *reinterpret_cast<const float2*>(tA + o); ra.x += bcoef*t2.x; ra.y += bcoef*t2.y; }
    if (tB){ const float2 t2 = *reinterpret_cast<const float2*>(tB + o); rb.x += bcoef*t2.x; rb.y += bcoef*t2.y; }
    *reinterpret_cast<float2*>(buf(outA) + o) = ra;
    *reinterpret_cast<float2*>(buf(outB) + o) = rb;
}

__global__ __launch_bounds__(256) void k_gather1(
        int outSel, const float* uExt, int uSel, const float* tExt, int tSel, int useT,
        float aScale, float bcoef, const float* __restrict__ lam){
    int node = (blockIdx.x*blockDim.x + threadIdx.x) >> 5;
    int l    = threadIdx.x & 31;
    if (node >= NN) return;
    const float* u = uExt ? uExt : buf(uSel);
    int beg = g_off[node], end = g_off[node+1];
    float2 acc = {0.f,0.f};
    for (int base = beg; base < end; base += 32){
        int n = end - base; if (n > 32) n = 32;
        int   sl = 0; float wl = 0.f;
        if (l < n){ sl = g_csc_src[base + l]; wl = g_csc_w[base + l]; }
        #pragma unroll 4
        for (int k = 0; k < n; k++){
            int   s  = __shfl_sync(0xffffffffu, sl, k);
            float wv = __shfl_sync(0xffffffffu, wl, k);
            float2 a = *reinterpret_cast<const float2*>(u + (size_t)s*DD + l*2);
            acc.x += wv*a.x; acc.y += wv*a.y;
        }
    }
    float c  = 2.f / lam[0];
    float ka = aScale*(c - 1.f);
    float kc = -aScale*c;
    size_t o = (size_t)node*DD + l*2;
    float2 uv = *reinterpret_cast<const float2*>(u + o);
    float2 r;
    r.x = ka*uv.x + kc*acc.x;  r.y = ka*uv.y + kc*acc.y;
    if (useT){
        const float* t = tExt ? tExt : buf(tSel);
        const float2 t2 = *reinterpret_cast<const float2*>(t + o);
        r.x += bcoef*t2.x; r.y += bcoef*t2.y;
    }
    *reinterpret_cast<float2*>(buf(outSel) + o) = r;
}

// ------- tf32 tensor-core Z / R / Gx GEMM + gate epilogue -------
// M = [X,X1,X2,H,H1,H2] tile (32 rows x 384, smem stride 388 = conflict-free
// A-frag LDS: 388 mod 32 = 4). 8 warps: warp = (mt = m-halftile, nq = n-quad).
// Each warp: 2 n-tiles x 3 gates, A-fragment shared across all 6 mma per k-step.
// mma.m16n8k8.row.col tf32, cvt.rna for RN rounding (~2.8e-4 RMS/operand).
#define SMS 388
__device__ __forceinline__ unsigned f2tf(float x){
    unsigned r; asm("cvt.rna.tf32.f32 %0, %1;" : "=r"(r) : "f"(x)); return r;
}
__device__ __forceinline__ void mma_tf32(float* acc, unsigned a0, unsigned a1,
                                         unsigned a2, unsigned a3,
                                         unsigned b0, unsigned b1){
    asm volatile(
        "mma.sync.aligned.m16n8k8.row.col.f32.tf32.tf32.f32 "
        "{%0,%1,%2,%3}, {%4,%5,%6,%7}, {%8,%9}, {%0,%1,%2,%3};\n"
        : "+f"(acc[0]), "+f"(acc[1]), "+f"(acc[2]), "+f"(acc[3])
        : "r"(a0), "r"(a1), "r"(a2), "r"(a3), "r"(b0), "r"(b1));
}

__global__ __launch_bounds__(256) void k_gates(const float* __restrict__ X,
                                               const float* __restrict__ H,
                                               const float* __restrict__ W,
                                               const float* __restrict__ B){
    extern __shared__ float sm[];          // 32*SMS floats (49664 B, dynamic)
    int tid = threadIdx.x;
    int r0  = blockIdx.x * 32;
    const float* vecs[6] = {X, g_X1, g_X2, H, g_H1, g_H2};
    for (int v = 0; v < 6; v++){
        const float* src = vecs[v];
        for (int i = tid; i < 32*64; i += 256){
            int r = i >> 6, cc = i & 63;
            int row = r0 + r;
            sm[r*SMS + v*64 + cc] = (row < NN) ? src[(size_t)row*64 + cc] : 0.f;
        }
    }
    __syncthreads();

    int warp = tid >> 5, lane = tid & 31;
    int mt  = warp & 1;                    // rows mt*16 .. mt*16+15
    int nq  = warp >> 1;                   // n-tiles 2*nq, 2*nq+1
    int gid = lane >> 2, tig = lane & 3;

    float accZ[2][4] = {}, accR[2][4] = {}, accG[2][4] = {};

    for (int v = 0; v < 6; v++){
        int kk = (v < 3) ? v : v - 3;
        const float* Wz = W + (size_t)(((v < 3 ? 0 : 1)*3 + kk))*4096;
        const float* Wr = W + (size_t)(((v < 3 ? 2 : 3)*3 + kk))*4096;
        const float* Wg = W + (size_t)(12 + kk)*4096;   // conv4, used when v<3
        bool hasG = (v < 3);
        #pragma unroll
        for (int ks = 0; ks < 8; ks++){
            int k0 = ks*8;
            // A fragment (shared by both n-tiles and all gates)
            const float* ab = &sm[(mt*16 + gid)*SMS + v*64 + k0 + tig];
            unsigned a0 = f2tf(ab[0]);
            unsigned a1 = f2tf(ab[8*SMS]);
            unsigned a2 = f2tf(ab[4]);
            unsigned a3 = f2tf(ab[8*SMS + 4]);
            #pragma unroll
            for (int nt = 0; nt < 2; nt++){
                int n0 = (nq*2 + nt)*8;
                int bi0 = (k0 + tig)*64 + n0 + gid;
                int bi1 = bi0 + 4*64;
                unsigned bz0 = f2tf(Wz[bi0]), bz1 = f2tf(Wz[bi1]);
                mma_tf32(accZ[nt], a0,a1,a2,a3, bz0,bz1);
                unsigned br0 = f2tf(Wr[bi0]), br1 = f2tf(Wr[bi1]);
                mma_tf32(accR[nt], a0,a1,a2,a3, br0,br1);
                if (hasG){
                    unsigned bg0 = f2tf(Wg[bi0]), bg1 = f2tf(Wg[bi1]);
                    mma_tf32(accG[nt], a0,a1,a2,a3, bg0,bg1);
                }
            }
        }
    }

    // epilogue: D-frag c at (row = gid + (c>=2)*8, col = 2*tig + (c&1))
    #pragma unroll
    for (int nt = 0; nt < 2; nt++){
        int n0 = (nq*2 + nt)*8;
        #pragma unroll
        for (int c = 0; c < 4; c++){
            int row = r0 + mt*16 + gid + ((c >> 1) ? 8 : 0);
            int col = n0 + 2*tig + (c & 1);
            if (row < NN){
                size_t o = (size_t)row*64 + col;
                float bz = B[col] + B[64+col];
                float br = B[128+col] + B[192+col];
                float z  = 1.f/(1.f + __expf(-(accZ[nt][c] + bz)));
                float rr = 1.f/(1.f + __expf(-(accR[nt][c] + br)));
                g_Z[o]  = z;
                g_Gx[o] = accG[nt][c] + B[256+col];
                g_HR[o] = H[o] * rr;
            }
        }
    }
}

// Gh = [HR,HR1,HR2]@W5 + b5; H_tilde = tanh(Gx+Gh); out = Z*H_tilde + (1-Z)*H
__global__ __launch_bounds__(256) void k_final(const float* __restrict__ H,
                                               const float* __restrict__ W,
                                               const float* __restrict__ B,
                                               float* __restrict__ out){
    __shared__ float smf[32*192];   // 24 KB
    int tid = threadIdx.x;
    int r0  = blockIdx.x * 32;
    const float* vecs[3] = {g_HR, g_HR1, g_HR2};
    for (int v = 0; v < 3; v++){
        const float* src = vecs[v];
        for (int i = tid; i < 32*64; i += 256){
            int r = i >> 6, cc = i & 63;
            int row = r0 + r;
            smf[r*192 + v*64 + cc] = (row < NN) ? src[(size_t)row*64 + cc] : 0.f;
        }
    }
    __syncthreads();

    int j  = tid & 63;
    int rg = tid >> 6;
    float acc[8] = {};
    for (int v = 0; v < 3; v++){
        const float* wp = W + (size_t)((5*3 + v)*64)*64 + j;
        for (int ii = 0; ii < 64; ii++){
            float wv = wp[ii*64];
            const float* mrow = &smf[(rg*8)*192 + v*64 + ii];
            #pragma unroll
            for (int r = 0; r < 8; r++) acc[r] += mrow[r*192]*wv;
        }
    }
    float b5 = B[320 + j];
    #pragma unroll
    for (int r = 0; r < 8; r++){
        int row = r0 + rg*8 + r;
        if (row < NN){
            size_t o = (size_t)row*64 + j;
            float ht = tanhf(g_Gx[o] + acc[r] + b5);
            float z  = g_Z[o];
            out[o] = z*ht + (1.f - z)*H[o];
        }
    }
}

extern "C" void kernel_launch(void* const* d_in, const int* in_sizes, int n_in,
                              void* d_out, int out_size){
    const float* X   = (const float*)d_in[0];
    const void*  ei  = d_in[1];
    const float* w   = (const float*)d_in[2];
    const float* H   = (const float*)d_in[3];
    const float* lam = (const float*)d_in[4];
    const float* W   = (const float*)d_in[5];
    const float* B   = (const float*)d_in[6];
    float* out = (float*)d_out;

    const int bN  = (NN + 255)/256;
    const int bE  = (EE + 255)/256;
    const int bGT = (NN*32 + 255)/256;     // warp-per-node gather
    const int bG  = (NN + 31)/32;          // 1563 blocks

    // unconditional (no static guards): cheap, idempotent, capture-safe
    const int SMEM_GATES = 32*SMS*4;       // 49664 B > 48K default -> opt in
    cudaFuncSetAttribute(k_gates, cudaFuncAttributeMaxDynamicSharedMemorySize, SMEM_GATES);

    // ---- CSC build ----
    k_detect<<<1, 32>>>(ei);
    k_zero  <<<bN, 256>>>();
    k_hist  <<<bE, 256>>>(ei, w);
    k_scan1 <<<NB, 256>>>();
    k_scan2 <<<1, 256>>>();
    k_scan3 <<<NB, 256>>>();
    k_place <<<bE, 256>>>(ei, w);

    // ---- Chebyshev bases: T1 = (c-1)v - cAv ; T2 = 2(c-1)T1 - 2cAT1 - v ----
    k_gather2<<<bGT, 256>>>(0, X, 0, nullptr,      2, H, 0, nullptr,      1.f,  0.f, lam);
    k_gather2<<<bGT, 256>>>(1, nullptr, 0, X,      3, nullptr, 2, H,      2.f, -1.f, lam);

    // ---- Z, R, Gx, HR = H*R (tf32 tensor cores) ----
    k_gates<<<bG, 256, SMEM_GATES>>>(X, H, W, B);

    // ---- HR chain ----
    k_gather1<<<bGT, 256>>>(5, nullptr, 4, nullptr, 0, 0, 1.f,  0.f, lam);
    k_gather1<<<bGT, 256>>>(6, nullptr, 5, nullptr, 4, 1, 2.f, -1.f, lam);

    // ---- Gh, H_tilde, output ----
    k_final<<<bG, 256>>>(H, W, B, out);
}